// round 9
// baseline (speedup 1.0000x reference)
#include <cuda_runtime.h>
#include <cuda_bf16.h>
#include <cstdint>

#define BATCH 8
#define SEQ   2048
#define DIM   128
#define EXP2_SCALE (0.08838834764831843f * 1.44269504088896340f)

typedef unsigned long long ull;

// ---------------- device scratch ----------------
__device__ float g_inv_rs[BATCH * SEQ];
__device__ __align__(16) __nv_bfloat16 g_qhi[BATCH * SEQ * DIM];
__device__ __align__(16) __nv_bfloat16 g_qlo[BATCH * SEQ * DIM];
__device__ __align__(16) __nv_bfloat16 g_vhi[BATCH * SEQ * DIM];  // w_hi after pass1
__device__ __align__(16) __nv_bfloat16 g_vlo[BATCH * SEQ * DIM];  // w_lo after pass1
__device__ __align__(16) __nv_bfloat16 g_uhi[(size_t)BATCH * SEQ * SEQ];
__device__ __align__(16) __nv_bfloat16 g_ulo[(size_t)BATCH * SEQ * SEQ];

// ---------------- cp.async ----------------
__device__ __forceinline__ void cp_async16(uint32_t smem_dst, const void* gsrc) {
    asm volatile("cp.async.ca.shared.global [%0], [%1], 16;\n"
                 :: "r"(smem_dst), "l"(gsrc));
}
#define CP_COMMIT() asm volatile("cp.async.commit_group;\n" ::: "memory")
#define CP_WAIT0()  asm volatile("cp.async.wait_group 0;\n" ::: "memory")

__device__ __forceinline__ uint32_t smem_u32(const void* p) {
    uint32_t a;
    asm("{ .reg .u64 t; cvta.to.shared.u64 t, %1; cvt.u32.u64 %0, t; }"
        : "=r"(a) : "l"(p));
    return a;
}

// ---------------- mma / ldmatrix ----------------
__device__ __forceinline__ void ldm4(unsigned* r, uint32_t addr) {
    asm volatile("ldmatrix.sync.aligned.m8n8.x4.shared.b16 {%0,%1,%2,%3}, [%4];"
                 : "=r"(r[0]), "=r"(r[1]), "=r"(r[2]), "=r"(r[3]) : "r"(addr));
}
__device__ __forceinline__ void ldm4t(unsigned* r, uint32_t addr) {
    asm volatile("ldmatrix.sync.aligned.m8n8.x4.trans.shared.b16 {%0,%1,%2,%3}, [%4];"
                 : "=r"(r[0]), "=r"(r[1]), "=r"(r[2]), "=r"(r[3]) : "r"(addr));
}
__device__ __forceinline__ void mma16816(float* d, const unsigned* a,
                                         const unsigned* b) {
    asm volatile(
        "mma.sync.aligned.m16n8k16.row.col.f32.bf16.bf16.f32 "
        "{%0,%1,%2,%3}, {%4,%5,%6,%7}, {%8,%9}, {%0,%1,%2,%3};"
        : "+f"(d[0]), "+f"(d[1]), "+f"(d[2]), "+f"(d[3])
        : "r"(a[0]), "r"(a[1]), "r"(a[2]), "r"(a[3]), "r"(b[0]), "r"(b[1]));
}

// =====================================================================
// split kernel: q,v -> bf16 hi/lo
// =====================================================================
__global__ void __launch_bounds__(256)
split_kernel(const float* __restrict__ q, const float* __restrict__ v) {
    int i = (blockIdx.x * 256 + threadIdx.x) * 4;
    float4 fq = *(const float4*)(q + i);
    float4 fv = *(const float4*)(v + i);
    float xq[4] = {fq.x, fq.y, fq.z, fq.w};
    float xv[4] = {fv.x, fv.y, fv.z, fv.w};
    __nv_bfloat16 qh[4], ql[4], vh[4], vl[4];
#pragma unroll
    for (int j = 0; j < 4; ++j) {
        qh[j] = __float2bfloat16(xq[j]);
        ql[j] = __float2bfloat16(xq[j] - __bfloat162float(qh[j]));
        vh[j] = __float2bfloat16(xv[j]);
        vl[j] = __float2bfloat16(xv[j] - __bfloat162float(vh[j]));
    }
    *(ull*)(g_qhi + i) = *(ull*)qh;
    *(ull*)(g_qlo + i) = *(ull*)ql;
    *(ull*)(g_vhi + i) = *(ull*)vh;
    *(ull*)(g_vlo + i) = *(ull*)vl;
}

// =====================================================================
// wsplit kernel (after pass1): w[i,d] = inv_rs[i]*v[i,d] -> bf16 hi/lo
// =====================================================================
__global__ void __launch_bounds__(256)
wsplit_kernel(const float* __restrict__ v) {
    int e = (blockIdx.x * 256 + threadIdx.x) * 4;
    float s = g_inv_rs[e >> 7];
    float4 f = *(const float4*)(v + e);
    float x[4] = {f.x * s, f.y * s, f.z * s, f.w * s};
    __nv_bfloat16 wh[4], wl[4];
#pragma unroll
    for (int j = 0; j < 4; ++j) {
        wh[j] = __float2bfloat16(x[j]);
        wl[j] = __float2bfloat16(x[j] - __bfloat162float(wh[j]));
    }
    *(ull*)(g_vhi + e) = *(ull*)wh;
    *(ull*)(g_vlo + e) = *(ull*)wl;
}

// =====================================================================
// Pass 1: u = exp(q.v^T/sqrt(D)) -> bf16 hi/lo; inv rowsums.
// CTA: 64 i-rows, 256 thr (8 warps: 2m x 4n, warp tile 32x16),
// j chunks of 64, depth-1 cp.async pipeline, one barrier per chunk. occ 2.
// =====================================================================
#define PITCH 272
#define VTILE (64 * PITCH)                  // 17408
#define OFF_QLO   0
#define OFF_VBUF(x) (VTILE + (x) * (2 * VTILE))
#define OFF_RS    (VTILE + 4 * VTILE)       // 87040
#define P1_SMEM   (OFF_RS + 64 * 4 * 4)     // 88064

// 64-row x 256B tile
__device__ __forceinline__ void stage_tile64(uint32_t dst,
                                             const __nv_bfloat16* src, int t) {
#pragma unroll
    for (int it = 0; it < 4; ++it) {
        int id = it * 256 + t;
        int r = id >> 4, c = id & 15;
        cp_async16(dst + r * PITCH + c * 16, src + r * 128 + c * 8);
    }
}

__global__ void __launch_bounds__(256, 2)
pass1_kernel() {
    extern __shared__ char sm[];
    const uint32_t smb = smem_u32(sm);
    float* rsbuf = (float*)(sm + OFF_RS);   // [64][4]

    const int b  = blockIdx.y;
    const int i0 = blockIdx.x * 64;
    const int t  = threadIdx.x;
    const int w  = t >> 5;
    const int l  = t & 31;
    const int wm = w & 1;        // m-tile (32 rows)
    const int wn = w >> 1;       // n-tile (16 cols)

    const __nv_bfloat16* qhg = g_qhi + ((size_t)b * SEQ + i0) * DIM;
    const __nv_bfloat16* qlg = g_qlo + ((size_t)b * SEQ + i0) * DIM;
    const __nv_bfloat16* vhg = g_vhi + (size_t)b * SEQ * DIM;
    const __nv_bfloat16* vlg = g_vlo + (size_t)b * SEQ * DIM;

    const int rA = (l & 7) + ((l >> 3) & 1) * 8;
    const int cA = (l >> 4) * 8;
    const int rB = (l & 7) + (l >> 4) * 8;
    const int cB = ((l >> 3) & 1) * 8;

    // ---- prologue: stage Qhi (into vbuf0) + Qlo ----
    stage_tile64(smb + OFF_VBUF(0), qhg, t);
    stage_tile64(smb + OFF_QLO,     qlg, t);
    CP_COMMIT();
    CP_WAIT0();
    __syncthreads();

    unsigned qh[2][8][4];
#pragma unroll
    for (int f = 0; f < 2; ++f)
#pragma unroll
        for (int k8 = 0; k8 < 8; ++k8) {
            uint32_t addr = smb + OFF_VBUF(0) +
                (wm * 32 + f * 16 + rA) * PITCH + (k8 * 16 + cA) * 2;
            ldm4(qh[f][k8], addr);
        }
    __syncthreads();   // all warps done reading staging area

    uint32_t qloA[2];
#pragma unroll
    for (int f = 0; f < 2; ++f)
        qloA[f] = smb + OFF_QLO + (wm * 32 + f * 16 + rA) * PITCH + cA * 2;
    const uint32_t bRowA = (wn * 16 + rB) * PITCH + cB * 2;

    // stage v chunk 0 into vbuf0
    stage_tile64(smb + OFF_VBUF(0),         vhg, t);
    stage_tile64(smb + OFF_VBUF(0) + VTILE, vlg, t);
    CP_COMMIT();

    // per-thread u output pointers
    __nv_bfloat16 *uh[2], *ul[2];
#pragma unroll
    for (int f = 0; f < 2; ++f) {
        size_t base = ((size_t)(b * SEQ + i0 + wm * 32 + f * 16 + (l >> 2))) * SEQ
                      + wn * 16 + (l & 3) * 2;
        uh[f] = g_uhi + base;
        ul[f] = g_ulo + base;
    }

    float rs[2][2] = {{0.f, 0.f}, {0.f, 0.f}};
    const int NCHUNK = SEQ / 64;   // 32

    for (int c = 0; c < NCHUNK; ++c) {
        CP_WAIT0();
        __syncthreads();   // chunk c visible; all warps done with chunk c-1 buf

        if (c + 1 < NCHUNK) {
            const uint32_t nb = smb + OFF_VBUF((c + 1) & 1);
            stage_tile64(nb,         vhg + (size_t)(c + 1) * 64 * DIM, t);
            stage_tile64(nb + VTILE, vlg + (size_t)(c + 1) * 64 * DIM, t);
            CP_COMMIT();
        }

        const uint32_t vh = smb + OFF_VBUF(c & 1);
        const uint32_t vl = vh + VTILE;

        float acc[2][2][4];
#pragma unroll
        for (int f = 0; f < 2; ++f)
#pragma unroll
            for (int h = 0; h < 2; ++h)
#pragma unroll
                for (int x = 0; x < 4; ++x) acc[f][h][x] = 0.0f;

#pragma unroll
        for (int k8 = 0; k8 < 8; ++k8) {
            unsigned bh4[4], bl4[4], al[2][4];
            ldm4(bh4, vh + bRowA + k8 * 32);
            ldm4(al[0], qloA[0] + k8 * 32);
            ldm4(al[1], qloA[1] + k8 * 32);
            ldm4(bl4, vl + bRowA + k8 * 32);
#pragma unroll
            for (int f = 0; f < 2; ++f)
#pragma unroll
                for (int h = 0; h < 2; ++h) {
                    mma16816(acc[f][h], qh[f][k8], &bh4[2 * h]);  // hi.hi
                    mma16816(acc[f][h], al[f],     &bh4[2 * h]);  // lo.hi
                    mma16816(acc[f][h], qh[f][k8], &bl4[2 * h]);  // hi.lo
                }
        }

        // ---- epilogue: exp + rowsum + bf16 hi/lo store ----
#pragma unroll
        for (int f = 0; f < 2; ++f)
#pragma unroll
            for (int h = 0; h < 2; ++h) {
                float e0 = exp2f(acc[f][h][0] * EXP2_SCALE);
                float e1 = exp2f(acc[f][h][1] * EXP2_SCALE);
                float e2 = exp2f(acc[f][h][2] * EXP2_SCALE);
                float e3 = exp2f(acc[f][h][3] * EXP2_SCALE);
                rs[f][0] += e0 + e1;
                rs[f][1] += e2 + e3;
                __nv_bfloat162 h01 = __floats2bfloat162_rn(e0, e1);
                __nv_bfloat162 h23 = __floats2bfloat162_rn(e2, e3);
                __nv_bfloat162 l01 = __floats2bfloat162_rn(
                    e0 - __bfloat162float(h01.x), e1 - __bfloat162float(h01.y));
                __nv_bfloat162 l23 = __floats2bfloat162_rn(
                    e2 - __bfloat162float(h23.x), e3 - __bfloat162float(h23.y));
                int off = c * 64 + h * 8;
                *(__nv_bfloat162*)(uh[f] + off)           = h01;
                *(__nv_bfloat162*)(uh[f] + off + 8 * SEQ) = h23;
                *(__nv_bfloat162*)(ul[f] + off)           = l01;
                *(__nv_bfloat162*)(ul[f] + off + 8 * SEQ) = l23;
            }
    }

    // ---- rowsums ----
#pragma unroll
    for (int f = 0; f < 2; ++f)
#pragma unroll
        for (int h = 0; h < 2; ++h) {
            rs[f][h] += __shfl_xor_sync(0xffffffffu, rs[f][h], 1);
            rs[f][h] += __shfl_xor_sync(0xffffffffu, rs[f][h], 2);
        }
    if ((l & 3) == 0) {
#pragma unroll
        for (int f = 0; f < 2; ++f)
#pragma unroll
            for (int h = 0; h < 2; ++h) {
                int row = wm * 32 + f * 16 + h * 8 + (l >> 2);
                rsbuf[row * 4 + wn] = rs[f][h];
            }
    }
    __syncthreads();
    if (t < 64)
        g_inv_rs[b * SEQ + i0 + t] = 1.0f /
            (rsbuf[t * 4] + rsbuf[t * 4 + 1] + rsbuf[t * 4 + 2] + rsbuf[t * 4 + 3]);
}

// =====================================================================
// Pass 2: out[j,d] = sum_i u[i,j]*w[i,d]; attn = (u_hi+u_lo)*inv_rs.
// CTA: 64 j x 128 d, 256 thr (8 warps: 2m x 4n, warp tile 32x32),
// i chunks of 64, depth-1 pipeline, one barrier per chunk. occ 2.
// =====================================================================
#define P2_I    64
#define UPITCH  144
#define WPITCH  272
#define UTILE   (P2_I * UPITCH)             // 9216
#define WTILE   (P2_I * WPITCH)             // 17408
#define P2_BUF  (2 * UTILE + 2 * WTILE)     // 53248
#define OFF_UH(x) ((x) * P2_BUF)
#define OFF_UL(x) ((x) * P2_BUF + UTILE)
#define OFF_WH(x) ((x) * P2_BUF + 2 * UTILE)
#define OFF_WL(x) ((x) * P2_BUF + 2 * UTILE + WTILE)
#define P2_SMEM   (2 * P2_BUF)              // 106496

__device__ __forceinline__ void stage_u64(uint32_t dst,
                                          const __nv_bfloat16* src, int t) {
#pragma unroll
    for (int it = 0; it < 2; ++it) {
        int id = it * 256 + t;
        int r = id >> 3, c = id & 7;
        cp_async16(dst + r * UPITCH + c * 16, src + (size_t)r * SEQ + c * 8);
    }
}
__device__ __forceinline__ void stage_w64(uint32_t dst,
                                          const __nv_bfloat16* src, int t) {
#pragma unroll
    for (int it = 0; it < 4; ++it) {
        int id = it * 256 + t;
        int r = id >> 4, c = id & 15;
        cp_async16(dst + r * WPITCH + c * 16, src + r * DIM + c * 8);
    }
}

__global__ void __launch_bounds__(256, 2)
pass2_kernel(float* __restrict__ attn, float* __restrict__ out) {
    extern __shared__ char sm[];
    const uint32_t smb = smem_u32(sm);

    const int b  = blockIdx.y;
    const int j0 = blockIdx.x * 64;
    const int t  = threadIdx.x;
    const int w  = t >> 5;
    const int l  = t & 31;
    const int wm = w & 1;        // j-subtile (32)
    const int wn = w >> 1;       // d-subtile (32)

    float* ab = attn + (size_t)b * SEQ * SEQ;
    const __nv_bfloat16* uhg = g_uhi + (size_t)b * SEQ * SEQ + j0;
    const __nv_bfloat16* ulg = g_ulo + (size_t)b * SEQ * SEQ + j0;
    const __nv_bfloat16* whg = g_vhi + (size_t)b * SEQ * DIM;
    const __nv_bfloat16* wlg = g_vlo + (size_t)b * SEQ * DIM;
    const float* irs = g_inv_rs + b * SEQ;
    float*       ob  = out + (size_t)b * SEQ * DIM;

    const int rAT = (l & 7) + ((l >> 4) & 1) * 8;
    const int cAT = ((l >> 3) & 1) * 8;
    const int rBT = (l & 7) + ((l >> 3) & 1) * 8;
    const int cBT = (l >> 4) * 8;

    // prologue: chunk 0
    stage_u64(smb + OFF_UH(0), uhg, t);
    stage_u64(smb + OFF_UL(0), ulg, t);
    stage_w64(smb + OFF_WH(0), whg, t);
    stage_w64(smb + OFF_WL(0), wlg, t);
    CP_COMMIT();

    float acc[2][4][4];
#pragma unroll
    for (int f = 0; f < 2; ++f)
#pragma unroll
        for (int n = 0; n < 4; ++n)
#pragma unroll
            for (int x = 0; x < 4; ++x) acc[f][n][x] = 0.0f;

    const int NCHUNK = SEQ / P2_I;   // 32

    for (int c = 0; c < NCHUNK; ++c) {
        const int bu = c & 1;
        const int i0c = c * P2_I;

        CP_WAIT0();
        __syncthreads();   // chunk c ready; all warps done with buffer !bu

        if (c + 1 < NCHUNK) {
            const int nb = (c + 1) & 1;
            stage_u64(smb + OFF_UH(nb), uhg + (size_t)(i0c + P2_I) * SEQ, t);
            stage_u64(smb + OFF_UL(nb), ulg + (size_t)(i0c + P2_I) * SEQ, t);
            stage_w64(smb + OFF_WH(nb), whg + (size_t)(i0c + P2_I) * DIM, t);
            stage_w64(smb + OFF_WL(nb), wlg + (size_t)(i0c + P2_I) * DIM, t);
            CP_COMMIT();
        }

        // ---- attn write: (u_hi + u_lo)*inv_rs -> gmem ----
#pragma unroll
        for (int it = 0; it < 2; ++it) {
            int row = (t >> 3) + it * 32;
            int g = t & 7;
            float s = __ldg(irs + i0c + row);
            uint32_t ha = smb + OFF_UH(bu) + row * UPITCH + g * 16;
            uint32_t la = smb + OFF_UL(bu) + row * UPITCH + g * 16;
            unsigned hr[4], lr[4];
            asm volatile("ld.shared.v4.b32 {%0,%1,%2,%3}, [%4];"
                         : "=r"(hr[0]), "=r"(hr[1]), "=r"(hr[2]), "=r"(hr[3]) : "r"(ha));
            asm volatile("ld.shared.v4.b32 {%0,%1,%2,%3}, [%4];"
                         : "=r"(lr[0]), "=r"(lr[1]), "=r"(lr[2]), "=r"(lr[3]) : "r"(la));
            float o[8];
#pragma unroll
            for (int x = 0; x < 4; ++x) {
                __nv_bfloat162 h2 = *(__nv_bfloat162*)&hr[x];
                __nv_bfloat162 l2 = *(__nv_bfloat162*)&lr[x];
                o[2 * x + 0] = (__bfloat162float(h2.x) + __bfloat162float(l2.x)) * s;
                o[2 * x + 1] = (__bfloat162float(h2.y) + __bfloat162float(l2.y)) * s;
            }
            float* grow = ab + (size_t)(i0c + row) * SEQ + j0 + g * 8;
            *(float4*)(grow)     = make_float4(o[0], o[1], o[2], o[3]);
            *(float4*)(grow + 4) = make_float4(o[4], o[5], o[6], o[7]);
        }

        // ---- MMA ----
        const uint32_t UH = smb + OFF_UH(bu);
        const uint32_t UL = smb + OFF_UL(bu);
        const uint32_t WH = smb + OFF_WH(bu);
        const uint32_t WL = smb + OFF_WL(bu);
#pragma unroll
        for (int k8 = 0; k8 < P2_I / 16; ++k8) {
            unsigned ahf[2][4], alf[2][4];
#pragma unroll
            for (int f = 0; f < 2; ++f) {
                uint32_t coff = (k8 * 16 + rAT) * UPITCH +
                                (wm * 32 + f * 16 + cAT) * 2;
                ldm4t(ahf[f], UH + coff);
                ldm4t(alf[f], UL + coff);
            }
            unsigned bh[2][4], bl[2][4];
#pragma unroll
            for (int p = 0; p < 2; ++p) {
                uint32_t coff = (k8 * 16 + rBT) * WPITCH +
                                (wn * 32 + p * 16 + cBT) * 2;
                ldm4t(bh[p], WH + coff);
                ldm4t(bl[p], WL + coff);
            }
#pragma unroll
            for (int p = 0; p < 2; ++p)
#pragma unroll
                for (int h = 0; h < 2; ++h) {
                    int n = 2 * p + h;
#pragma unroll
                    for (int f = 0; f < 2; ++f) {
                        mma16816(acc[f][n], ahf[f], &bh[p][2 * h]);  // hi.hi
                        mma16816(acc[f][n], alf[f], &bh[p][2 * h]);  // lo.hi
                        mma16816(acc[f][n], ahf[f], &bl[p][2 * h]);  // hi.lo
                    }
                }
        }
    }

    // ---- store out[j,d] ----
#pragma unroll
    for (int f = 0; f < 2; ++f) {
        int jr = j0 + wm * 32 + f * 16 + (l >> 2);
        float* r0 = ob + (size_t)jr * DIM + wn * 32 + (l & 3) * 2;
#pragma unroll
        for (int n = 0; n < 4; ++n) {
            *(float2*)(r0 + n * 8)           = make_float2(acc[f][n][0], acc[f][n][1]);
            *(float2*)(r0 + n * 8 + 8 * DIM) = make_float2(acc[f][n][2], acc[f][n][3]);
        }
    }
}

// =====================================================================
extern "C" void kernel_launch(void* const* d_in, const int* in_sizes, int n_in,
                              void* d_out, int out_size) {
    const float* q = (const float*)d_in[0];
    // d_in[1] (k) unused by the reference
    const float* v = (const float*)d_in[2];

    float* out  = (float*)d_out;                      // [8,2048,128]
    float* attn = out + (size_t)BATCH * SEQ * DIM;    // [8,2048,2048]

    cudaFuncSetAttribute(pass1_kernel,
                         cudaFuncAttributeMaxDynamicSharedMemorySize, P1_SMEM);
    cudaFuncSetAttribute(pass2_kernel,
                         cudaFuncAttributeMaxDynamicSharedMemorySize, P2_SMEM);

    split_kernel<<<(BATCH * SEQ * DIM) / (256 * 4), 256>>>(q, v);

    dim3 g1(SEQ / 64, BATCH);
    pass1_kernel<<<g1, 256, P1_SMEM>>>();

    wsplit_kernel<<<(BATCH * SEQ * DIM) / (256 * 4), 256>>>(v);

    dim3 g2(SEQ / 64, BATCH);
    pass2_kernel<<<g2, 256, P2_SMEM>>>(attn, out);
}

// round 10
// speedup vs baseline: 1.0202x; 1.0202x over previous
#include <cuda_runtime.h>
#include <cuda_bf16.h>
#include <cstdint>

#define BATCH 8
#define SEQ   2048
#define DIM   128
#define EXP2_SCALE (0.08838834764831843f * 1.44269504088896340f)

typedef unsigned long long ull;

// ---------------- device scratch ----------------
__device__ float g_inv_rs[BATCH * SEQ];
__device__ __align__(16) __nv_bfloat16 g_qhi[BATCH * SEQ * DIM];
__device__ __align__(16) __nv_bfloat16 g_qlo[BATCH * SEQ * DIM];
__device__ __align__(16) __nv_bfloat16 g_vhi[BATCH * SEQ * DIM];  // w_hi after pass1
__device__ __align__(16) __nv_bfloat16 g_vlo[BATCH * SEQ * DIM];  // w_lo after pass1
__device__ __align__(16) __nv_bfloat16 g_uhi[(size_t)BATCH * SEQ * SEQ];
__device__ __align__(16) __nv_bfloat16 g_ulo[(size_t)BATCH * SEQ * SEQ];

// ---------------- cp.async ----------------
__device__ __forceinline__ void cp_async16(uint32_t smem_dst, const void* gsrc) {
    asm volatile("cp.async.ca.shared.global [%0], [%1], 16;\n"
                 :: "r"(smem_dst), "l"(gsrc));
}
#define CP_COMMIT() asm volatile("cp.async.commit_group;\n" ::: "memory")
#define CP_WAIT0()  asm volatile("cp.async.wait_group 0;\n" ::: "memory")
#define CP_WAIT1()  asm volatile("cp.async.wait_group 1;\n" ::: "memory")
#define CP_WAIT2()  asm volatile("cp.async.wait_group 2;\n" ::: "memory")

__device__ __forceinline__ uint32_t smem_u32(const void* p) {
    uint32_t a;
    asm("{ .reg .u64 t; cvta.to.shared.u64 t, %1; cvt.u32.u64 %0, t; }"
        : "=r"(a) : "l"(p));
    return a;
}

// ---------------- mma / ldmatrix ----------------
__device__ __forceinline__ void ldm4(unsigned* r, uint32_t addr) {
    asm volatile("ldmatrix.sync.aligned.m8n8.x4.shared.b16 {%0,%1,%2,%3}, [%4];"
                 : "=r"(r[0]), "=r"(r[1]), "=r"(r[2]), "=r"(r[3]) : "r"(addr));
}
__device__ __forceinline__ void ldm4t(unsigned* r, uint32_t addr) {
    asm volatile("ldmatrix.sync.aligned.m8n8.x4.trans.shared.b16 {%0,%1,%2,%3}, [%4];"
                 : "=r"(r[0]), "=r"(r[1]), "=r"(r[2]), "=r"(r[3]) : "r"(addr));
}
__device__ __forceinline__ void mma16816(float* d, const unsigned* a,
                                         const unsigned* b) {
    asm volatile(
        "mma.sync.aligned.m16n8k16.row.col.f32.bf16.bf16.f32 "
        "{%0,%1,%2,%3}, {%4,%5,%6,%7}, {%8,%9}, {%0,%1,%2,%3};"
        : "+f"(d[0]), "+f"(d[1]), "+f"(d[2]), "+f"(d[3])
        : "r"(a[0]), "r"(a[1]), "r"(a[2]), "r"(a[3]), "r"(b[0]), "r"(b[1]));
}

// =====================================================================
// split kernel: q,v -> bf16 hi/lo
// =====================================================================
__global__ void __launch_bounds__(256)
split_kernel(const float* __restrict__ q, const float* __restrict__ v) {
    int i = (blockIdx.x * 256 + threadIdx.x) * 4;
    float4 fq = *(const float4*)(q + i);
    float4 fv = *(const float4*)(v + i);
    float xq[4] = {fq.x, fq.y, fq.z, fq.w};
    float xv[4] = {fv.x, fv.y, fv.z, fv.w};
    __nv_bfloat16 qh[4], ql[4], vh[4], vl[4];
#pragma unroll
    for (int j = 0; j < 4; ++j) {
        qh[j] = __float2bfloat16(xq[j]);
        ql[j] = __float2bfloat16(xq[j] - __bfloat162float(qh[j]));
        vh[j] = __float2bfloat16(xv[j]);
        vl[j] = __float2bfloat16(xv[j] - __bfloat162float(vh[j]));
    }
    *(ull*)(g_qhi + i) = *(ull*)qh;
    *(ull*)(g_qlo + i) = *(ull*)ql;
    *(ull*)(g_vhi + i) = *(ull*)vh;
    *(ull*)(g_vlo + i) = *(ull*)vl;
}

// =====================================================================
// wsplit kernel (after pass1): w[i,d] = inv_rs[i]*v[i,d] -> bf16 hi/lo
// =====================================================================
__global__ void __launch_bounds__(256)
wsplit_kernel(const float* __restrict__ v) {
    int e = (blockIdx.x * 256 + threadIdx.x) * 4;
    float s = g_inv_rs[e >> 7];
    float4 f = *(const float4*)(v + e);
    float x[4] = {f.x * s, f.y * s, f.z * s, f.w * s};
    __nv_bfloat16 wh[4], wl[4];
#pragma unroll
    for (int j = 0; j < 4; ++j) {
        wh[j] = __float2bfloat16(x[j]);
        wl[j] = __float2bfloat16(x[j] - __bfloat162float(wh[j]));
    }
    *(ull*)(g_vhi + e) = *(ull*)wh;
    *(ull*)(g_vlo + e) = *(ull*)wl;
}

// =====================================================================
// Pass 1: u = exp(q.v^T/sqrt(D)) -> bf16 hi/lo; inv rowsums.
// CTA: 128 i-rows, 256 thr (8 warps: 4m x 2n), j chunks of 128. occ 1.
// =====================================================================
#define PITCH 272
#define TILE_B (128 * PITCH)
#define OFF_QLO   0
#define OFF_VBUF(x) (TILE_B + (x) * (2 * TILE_B))
#define OFF_RS    (TILE_B + 4 * TILE_B)
#define P1_SMEM   (OFF_RS + 128 * 2 * 4)

__device__ __forceinline__ void stage_tile(uint32_t dst,
                                           const __nv_bfloat16* src, int t) {
#pragma unroll
    for (int it = 0; it < 8; ++it) {
        int id = it * 256 + t;
        int r = id >> 4, c = id & 15;
        cp_async16(dst + r * PITCH + c * 16, src + r * 128 + c * 8);
    }
}

__global__ void __launch_bounds__(256, 1)
pass1_kernel() {
    extern __shared__ char sm[];
    const uint32_t smb = smem_u32(sm);
    float* rsbuf = (float*)(sm + OFF_RS);

    const int b  = blockIdx.y;
    const int i0 = blockIdx.x * 128;
    const int t  = threadIdx.x;
    const int w  = t >> 5;
    const int l  = t & 31;
    const int wm = w & 3;
    const int wn = w >> 2;

    const __nv_bfloat16* qhg = g_qhi + ((size_t)b * SEQ + i0) * DIM;
    const __nv_bfloat16* qlg = g_qlo + ((size_t)b * SEQ + i0) * DIM;
    const __nv_bfloat16* vhg = g_vhi + (size_t)b * SEQ * DIM;
    const __nv_bfloat16* vlg = g_vlo + (size_t)b * SEQ * DIM;

    const int rA = (l & 7) + ((l >> 3) & 1) * 8;
    const int cA = (l >> 4) * 8;
    const int rB = (l & 7) + (l >> 4) * 8;
    const int cB = ((l >> 3) & 1) * 8;

    stage_tile(smb + OFF_VBUF(0), qhg, t);
    stage_tile(smb + OFF_QLO,     qlg, t);
    CP_COMMIT();
    CP_WAIT0();
    __syncthreads();

    unsigned qh[2][8][4];
#pragma unroll
    for (int f = 0; f < 2; ++f)
#pragma unroll
        for (int k8 = 0; k8 < 8; ++k8) {
            uint32_t addr = smb + OFF_VBUF(0) +
                (wm * 32 + f * 16 + rA) * PITCH + (k8 * 16 + cA) * 2;
            ldm4(qh[f][k8], addr);
        }
    __syncthreads();

    uint32_t qloA[2];
#pragma unroll
    for (int f = 0; f < 2; ++f)
        qloA[f] = smb + OFF_QLO + (wm * 32 + f * 16 + rA) * PITCH + cA * 2;

    uint32_t bRow[4];
#pragma unroll
    for (int p = 0; p < 4; ++p)
        bRow[p] = (wn * 64 + p * 16 + rB) * PITCH + cB * 2;

    stage_tile(smb + OFF_VBUF(0),          vhg, t);
    stage_tile(smb + OFF_VBUF(0) + TILE_B, vlg, t);
    CP_COMMIT();
    stage_tile(smb + OFF_VBUF(1),          vhg + 128 * DIM, t);
    stage_tile(smb + OFF_VBUF(1) + TILE_B, vlg + 128 * DIM, t);
    CP_COMMIT();

    __nv_bfloat16 *uh[2], *ul[2];
#pragma unroll
    for (int f = 0; f < 2; ++f) {
        size_t base = ((size_t)(b * SEQ + i0 + wm * 32 + f * 16 + (l >> 2))) * SEQ
                      + wn * 64 + (l & 3) * 2;
        uh[f] = g_uhi + base;
        ul[f] = g_ulo + base;
    }

    float rs[2][2] = {{0.f, 0.f}, {0.f, 0.f}};
    const int NCHUNK = SEQ / 128;

    for (int c = 0; c < NCHUNK; ++c) {
        CP_WAIT1();
        __syncthreads();

        const uint32_t vh = smb + OFF_VBUF(c & 1);
        const uint32_t vl = vh + TILE_B;

        float acc[2][8][4];
#pragma unroll
        for (int f = 0; f < 2; ++f)
#pragma unroll
            for (int n = 0; n < 8; ++n)
#pragma unroll
                for (int x = 0; x < 4; ++x) acc[f][n][x] = 0.0f;

#pragma unroll
        for (int k8 = 0; k8 < 8; ++k8) {
            unsigned bh[4][4];
#pragma unroll
            for (int p = 0; p < 4; ++p)
                ldm4(bh[p], vh + bRow[p] + k8 * 32);
            unsigned al[2][4];
            ldm4(al[0], qloA[0] + k8 * 32);
            ldm4(al[1], qloA[1] + k8 * 32);
#pragma unroll
            for (int p = 0; p < 4; ++p)
#pragma unroll
                for (int h = 0; h < 2; ++h) {
                    const unsigned* bb = &bh[p][2 * h];
                    int n = 2 * p + h;
                    mma16816(acc[0][n], qh[0][k8], bb);
                    mma16816(acc[1][n], qh[1][k8], bb);
                    mma16816(acc[0][n], al[0], bb);
                    mma16816(acc[1][n], al[1], bb);
                }
            unsigned bl[4][4];
#pragma unroll
            for (int p = 0; p < 4; ++p)
                ldm4(bl[p], vl + bRow[p] + k8 * 32);
#pragma unroll
            for (int p = 0; p < 4; ++p)
#pragma unroll
                for (int h = 0; h < 2; ++h) {
                    const unsigned* bb = &bl[p][2 * h];
                    int n = 2 * p + h;
                    mma16816(acc[0][n], qh[0][k8], bb);
                    mma16816(acc[1][n], qh[1][k8], bb);
                }
        }

        __syncthreads();

        if (c + 2 < NCHUNK) {
            const uint32_t nb = smb + OFF_VBUF(c & 1);
            stage_tile(nb,          vhg + (size_t)(c + 2) * 128 * DIM, t);
            stage_tile(nb + TILE_B, vlg + (size_t)(c + 2) * 128 * DIM, t);
        }
        CP_COMMIT();

        // ---- epilogue: exp + rowsum + bf16 hi/lo store (trunc split) ----
#pragma unroll
        for (int f = 0; f < 2; ++f) {
#pragma unroll
            for (int n = 0; n < 8; ++n) {
                float e0 = exp2f(acc[f][n][0] * EXP2_SCALE);
                float e1 = exp2f(acc[f][n][1] * EXP2_SCALE);
                float e2 = exp2f(acc[f][n][2] * EXP2_SCALE);
                float e3 = exp2f(acc[f][n][3] * EXP2_SCALE);
                rs[f][0] += e0 + e1;
                rs[f][1] += e2 + e3;
                unsigned b0 = __float_as_uint(e0), b1 = __float_as_uint(e1);
                unsigned b2 = __float_as_uint(e2), b3 = __float_as_uint(e3);
                float h0 = __uint_as_float(b0 & 0xffff0000u);
                float h1 = __uint_as_float(b1 & 0xffff0000u);
                float h2 = __uint_as_float(b2 & 0xffff0000u);
                float h3 = __uint_as_float(b3 & 0xffff0000u);
                unsigned hp01 = __byte_perm(b0, b1, 0x7632);
                unsigned hp23 = __byte_perm(b2, b3, 0x7632);
                __nv_bfloat162 l01 = __floats2bfloat162_rn(e0 - h0, e1 - h1);
                __nv_bfloat162 l23 = __floats2bfloat162_rn(e2 - h2, e3 - h3);
                int o0 = c * 128 + n * 8;
                *(unsigned*)(uh[f] + o0)           = hp01;
                *(unsigned*)(uh[f] + o0 + 8 * SEQ) = hp23;
                *(__nv_bfloat162*)(ul[f] + o0)           = l01;
                *(__nv_bfloat162*)(ul[f] + o0 + 8 * SEQ) = l23;
            }
        }
    }

#pragma unroll
    for (int f = 0; f < 2; ++f)
#pragma unroll
        for (int h = 0; h < 2; ++h) {
            rs[f][h] += __shfl_xor_sync(0xffffffffu, rs[f][h], 1);
            rs[f][h] += __shfl_xor_sync(0xffffffffu, rs[f][h], 2);
        }
    if ((l & 3) == 0) {
#pragma unroll
        for (int f = 0; f < 2; ++f)
#pragma unroll
            for (int h = 0; h < 2; ++h) {
                int row = wm * 32 + f * 16 + h * 8 + (l >> 2);
                rsbuf[row * 2 + wn] = rs[f][h];
            }
    }
    __syncthreads();
    if (t < 128)
        g_inv_rs[b * SEQ + i0 + t] = 1.0f / (rsbuf[t * 2] + rsbuf[t * 2 + 1]);
}

// =====================================================================
// Pass 2: out[j,d] = sum_i u[i,j]*w[i,d]; attn = (u_hi+u_lo)*inv_rs.
// CTA: 64 j x 128 d, 256 thr (8 warps: 2m x 4n, warp tile 32x32).
// 64 chunks of 32 i, 4-stage cp.async pipeline (wait_group 2),
// one barrier per chunk. occ 2.
// =====================================================================
#define P2_I    32
#define UPITCH  144
#define WPITCH  272
#define USZ     (P2_I * UPITCH)            // 4608
#define WSZ     (P2_I * WPITCH)            // 8704
#define STG_SZ  (2 * USZ + 2 * WSZ)        // 26624
#define OFF_UH(s) ((s) * STG_SZ)
#define OFF_UL(s) ((s) * STG_SZ + USZ)
#define OFF_WH(s) ((s) * STG_SZ + 2 * USZ)
#define OFF_WL(s) ((s) * STG_SZ + 2 * USZ + WSZ)
#define P2_SMEM   (4 * STG_SZ)             // 106496

__device__ __forceinline__ void stage_u32r(uint32_t dst,
                                           const __nv_bfloat16* src, int t) {
    int r = t >> 3, c = t & 7;
    cp_async16(dst + r * UPITCH + c * 16, src + (size_t)r * SEQ + c * 8);
}
__device__ __forceinline__ void stage_w32r(uint32_t dst,
                                           const __nv_bfloat16* src, int t) {
#pragma unroll
    for (int it = 0; it < 2; ++it) {
        int id = it * 256 + t;
        int r = id >> 4, c = id & 15;
        cp_async16(dst + r * WPITCH + c * 16, src + r * DIM + c * 8);
    }
}

__global__ void __launch_bounds__(256, 2)
pass2_kernel(float* __restrict__ attn, float* __restrict__ out) {
    extern __shared__ char sm[];
    const uint32_t smb = smem_u32(sm);

    const int b  = blockIdx.y;
    const int j0 = blockIdx.x * 64;
    const int t  = threadIdx.x;
    const int w  = t >> 5;
    const int l  = t & 31;
    const int wm = w & 1;        // j-subtile (32)
    const int wn = w >> 1;       // d-subtile (32)

    float* ab = attn + (size_t)b * SEQ * SEQ;
    const __nv_bfloat16* uhg = g_uhi + (size_t)b * SEQ * SEQ + j0;
    const __nv_bfloat16* ulg = g_ulo + (size_t)b * SEQ * SEQ + j0;
    const __nv_bfloat16* whg = g_vhi + (size_t)b * SEQ * DIM;
    const __nv_bfloat16* wlg = g_vlo + (size_t)b * SEQ * DIM;
    const float* irs = g_inv_rs + b * SEQ;
    float*       ob  = out + (size_t)b * SEQ * DIM;

    const int rAT = (l & 7) + ((l >> 4) & 1) * 8;
    const int cAT = ((l >> 3) & 1) * 8;
    const int rBT = (l & 7) + ((l >> 3) & 1) * 8;
    const int cBT = (l >> 4) * 8;

    const int NCHUNK = SEQ / P2_I;   // 64

    // prologue: stages 0,1,2 (separate commit groups)
#pragma unroll
    for (int c = 0; c < 3; ++c) {
        const int s = c;
        stage_u32r(smb + OFF_UH(s), uhg + (size_t)c * P2_I * SEQ, t);
        stage_u32r(smb + OFF_UL(s), ulg + (size_t)c * P2_I * SEQ, t);
        stage_w32r(smb + OFF_WH(s), whg + (size_t)c * P2_I * DIM, t);
        stage_w32r(smb + OFF_WL(s), wlg + (size_t)c * P2_I * DIM, t);
        CP_COMMIT();
    }

    float acc[2][4][4];
#pragma unroll
    for (int f = 0; f < 2; ++f)
#pragma unroll
        for (int n = 0; n < 4; ++n)
#pragma unroll
            for (int x = 0; x < 4; ++x) acc[f][n][x] = 0.0f;

    for (int c = 0; c < NCHUNK; ++c) {
        const int st  = c & 3;
        const int i0c = c * P2_I;

        CP_WAIT2();        // stage c landed (c+1, c+2 still in flight)
        __syncthreads();   // all threads finished consuming chunk c-1

        // issue stage c+3 into slot (c+3)&3 == (c-1)&3 (free after barrier)
        if (c + 3 < NCHUNK) {
            const int ns = (c + 3) & 3;
            const size_t io = (size_t)(c + 3) * P2_I;
            stage_u32r(smb + OFF_UH(ns), uhg + io * SEQ, t);
            stage_u32r(smb + OFF_UL(ns), ulg + io * SEQ, t);
            stage_w32r(smb + OFF_WH(ns), whg + io * DIM, t);
            stage_w32r(smb + OFF_WL(ns), wlg + io * DIM, t);
        }
        CP_COMMIT();       // empty group at tail keeps wait_group counting exact

        // ---- attn write: (u_hi + u_lo)*inv_rs -> gmem ----
        {
            int row = t >> 3, g = t & 7;
            float s = __ldg(irs + i0c + row);
            uint32_t ha = smb + OFF_UH(st) + row * UPITCH + g * 16;
            uint32_t la = smb + OFF_UL(st) + row * UPITCH + g * 16;
            unsigned hr[4], lr[4];
            asm volatile("ld.shared.v4.b32 {%0,%1,%2,%3}, [%4];"
                         : "=r"(hr[0]), "=r"(hr[1]), "=r"(hr[2]), "=r"(hr[3]) : "r"(ha));
            asm volatile("ld.shared.v4.b32 {%0,%1,%2,%3}, [%4];"
                         : "=r"(lr[0]), "=r"(lr[1]), "=r"(lr[2]), "=r"(lr[3]) : "r"(la));
            float o[8];
#pragma unroll
            for (int x = 0; x < 4; ++x) {
                __nv_bfloat162 h2 = *(__nv_bfloat162*)&hr[x];
                __nv_bfloat162 l2 = *(__nv_bfloat162*)&lr[x];
                o[2 * x + 0] = (__bfloat162float(h2.x) + __bfloat162float(l2.x)) * s;
                o[2 * x + 1] = (__bfloat162float(h2.y) + __bfloat162float(l2.y)) * s;
            }
            float* grow = ab + (size_t)(i0c + row) * SEQ + j0 + g * 8;
            *(float4*)(grow)     = make_float4(o[0], o[1], o[2], o[3]);
            *(float4*)(grow + 4) = make_float4(o[4], o[5], o[6], o[7]);
        }

        // ---- MMA ----
        const uint32_t UH = smb + OFF_UH(st);
        const uint32_t UL = smb + OFF_UL(st);
        const uint32_t WH = smb + OFF_WH(st);
        const uint32_t WL = smb + OFF_WL(st);
#pragma unroll
        for (int k8 = 0; k8 < P2_I / 16; ++k8) {
            unsigned ahf[2][4], alf[2][4];
#pragma unroll
            for (int f = 0; f < 2; ++f) {
                uint32_t coff = (k8 * 16 + rAT) * UPITCH +
                                (wm * 32 + f * 16 + cAT) * 2;
                ldm4t(ahf[f], UH + coff);
                ldm4t(alf[f], UL + coff);
            }
            unsigned bh[2][4], bl[2][4];
#pragma unroll
            for (int p = 0; p < 2; ++p) {
                uint32_t coff = (k8 * 16 + rBT) * WPITCH +
                                (wn * 32 + p * 16 + cBT) * 2;
                ldm4t(bh[p], WH + coff);
                ldm4t(bl[p], WL + coff);
            }
#pragma unroll
            for (int p = 0; p < 2; ++p)
#pragma unroll
                for (int h = 0; h < 2; ++h) {
                    int n = 2 * p + h;
#pragma unroll
                    for (int f = 0; f < 2; ++f) {
                        mma16816(acc[f][n], ahf[f], &bh[p][2 * h]);  // hi.hi
                        mma16816(acc[f][n], alf[f], &bh[p][2 * h]);  // lo.hi
                        mma16816(acc[f][n], ahf[f], &bl[p][2 * h]);  // hi.lo
                    }
                }
        }
    }

    // ---- store out[j,d] ----
#pragma unroll
    for (int f = 0; f < 2; ++f) {
        int jr = j0 + wm * 32 + f * 16 + (l >> 2);
        float* r0 = ob + (size_t)jr * DIM + wn * 32 + (l & 3) * 2;
#pragma unroll
        for (int n = 0; n < 4; ++n) {
            *(float2*)(r0 + n * 8)           = make_float2(acc[f][n][0], acc[f][n][1]);
            *(float2*)(r0 + n * 8 + 8 * DIM) = make_float2(acc[f][n][2], acc[f][n][3]);
        }
    }
}

// =====================================================================
extern "C" void kernel_launch(void* const* d_in, const int* in_sizes, int n_in,
                              void* d_out, int out_size) {
    const float* q = (const float*)d_in[0];
    // d_in[1] (k) unused by the reference
    const float* v = (const float*)d_in[2];

    float* out  = (float*)d_out;                      // [8,2048,128]
    float* attn = out + (size_t)BATCH * SEQ * DIM;    // [8,2048,2048]

    cudaFuncSetAttribute(pass1_kernel,
                         cudaFuncAttributeMaxDynamicSharedMemorySize, P1_SMEM);
    cudaFuncSetAttribute(pass2_kernel,
                         cudaFuncAttributeMaxDynamicSharedMemorySize, P2_SMEM);

    split_kernel<<<(BATCH * SEQ * DIM) / (256 * 4), 256>>>(q, v);

    dim3 g1(SEQ / 128, BATCH);
    pass1_kernel<<<g1, 256, P1_SMEM>>>();

    wsplit_kernel<<<(BATCH * SEQ * DIM) / (256 * 4), 256>>>(v);

    dim3 g2(SEQ / 64, BATCH);
    pass2_kernel<<<g2, 256, P2_SMEM>>>(attn, out);
}

// round 12
// speedup vs baseline: 1.3270x; 1.3007x over previous
#include <cuda_runtime.h>
#include <cuda_fp16.h>
#include <cstdint>

#define BATCH 8
#define SEQ   2048
#define DIM   128
#define EXP2_SCALE (0.08838834764831843f * 1.44269504088896340f)

typedef unsigned long long ull;

// ---------------- device scratch ----------------
__device__ float g_inv_rs[BATCH * SEQ];
__device__ __align__(16) __half g_qhi[BATCH * SEQ * DIM];
__device__ __align__(16) __half g_qlo[BATCH * SEQ * DIM];
__device__ __align__(16) __half g_vhi[BATCH * SEQ * DIM];  // w_hi after pass1
__device__ __align__(16) __half g_vlo[BATCH * SEQ * DIM];
__device__ __align__(16) __half g_uhi[(size_t)BATCH * SEQ * SEQ];
__device__ __align__(16) __half g_ulo[(size_t)BATCH * SEQ * SEQ];

// ---------------- cp.async ----------------
__device__ __forceinline__ void cp_async16(uint32_t smem_dst, const void* gsrc) {
    asm volatile("cp.async.ca.shared.global [%0], [%1], 16;\n"
                 :: "r"(smem_dst), "l"(gsrc));
}
#define CP_COMMIT() asm volatile("cp.async.commit_group;\n" ::: "memory")
#define CP_WAIT0()  asm volatile("cp.async.wait_group 0;\n" ::: "memory")
#define CP_WAIT1()  asm volatile("cp.async.wait_group 1;\n" ::: "memory")
#define CP_WAIT2()  asm volatile("cp.async.wait_group 2;\n" ::: "memory")

__device__ __forceinline__ uint32_t smem_u32(const void* p) {
    uint32_t a;
    asm("{ .reg .u64 t; cvta.to.shared.u64 t, %1; cvt.u32.u64 %0, t; }"
        : "=r"(a) : "l"(p));
    return a;
}

// ---------------- mma / ldmatrix (fp16) ----------------
__device__ __forceinline__ void ldm4(unsigned* r, uint32_t addr) {
    asm volatile("ldmatrix.sync.aligned.m8n8.x4.shared.b16 {%0,%1,%2,%3}, [%4];"
                 : "=r"(r[0]), "=r"(r[1]), "=r"(r[2]), "=r"(r[3]) : "r"(addr));
}
__device__ __forceinline__ void ldm4t(unsigned* r, uint32_t addr) {
    asm volatile("ldmatrix.sync.aligned.m8n8.x4.trans.shared.b16 {%0,%1,%2,%3}, [%4];"
                 : "=r"(r[0]), "=r"(r[1]), "=r"(r[2]), "=r"(r[3]) : "r"(addr));
}
__device__ __forceinline__ void mma16816(float* d, const unsigned* a,
                                         const unsigned* b) {
    asm volatile(
        "mma.sync.aligned.m16n8k16.row.col.f32.f16.f16.f32 "
        "{%0,%1,%2,%3}, {%4,%5,%6,%7}, {%8,%9}, {%0,%1,%2,%3};"
        : "+f"(d[0]), "+f"(d[1]), "+f"(d[2]), "+f"(d[3])
        : "r"(a[0]), "r"(a[1]), "r"(a[2]), "r"(a[3]), "r"(b[0]), "r"(b[1]));
}

// =====================================================================
// split kernel: q,v -> fp16 hi/lo
// =====================================================================
__global__ void __launch_bounds__(256)
split_kernel(const float* __restrict__ q, const float* __restrict__ v) {
    int i = (blockIdx.x * 256 + threadIdx.x) * 4;
    float4 fq = *(const float4*)(q + i);
    float4 fv = *(const float4*)(v + i);
    float xq[4] = {fq.x, fq.y, fq.z, fq.w};
    float xv[4] = {fv.x, fv.y, fv.z, fv.w};
    __half qh[4], ql[4], vh[4], vl[4];
#pragma unroll
    for (int j = 0; j < 4; ++j) {
        qh[j] = __float2half_rn(xq[j]);
        ql[j] = __float2half_rn(xq[j] - __half2float(qh[j]));
        vh[j] = __float2half_rn(xv[j]);
        vl[j] = __float2half_rn(xv[j] - __half2float(vh[j]));
    }
    *(ull*)(g_qhi + i) = *(ull*)qh;
    *(ull*)(g_qlo + i) = *(ull*)ql;
    *(ull*)(g_vhi + i) = *(ull*)vh;
    *(ull*)(g_vlo + i) = *(ull*)vl;
}

// =====================================================================
// wsplit kernel (after pass1): w_hi[i,d] = fp16(inv_rs[i]*v[i,d])
// (2-term pass2 needs no w_lo)
// =====================================================================
__global__ void __launch_bounds__(256)
wsplit_kernel(const float* __restrict__ v) {
    int e = (blockIdx.x * 256 + threadIdx.x) * 4;
    float s = g_inv_rs[e >> 7];
    float4 f = *(const float4*)(v + e);
    __half wh[4];
    wh[0] = __float2half_rn(f.x * s);
    wh[1] = __float2half_rn(f.y * s);
    wh[2] = __float2half_rn(f.z * s);
    wh[3] = __float2half_rn(f.w * s);
    *(ull*)(g_vhi + e) = *(ull*)wh;
}

// =====================================================================
// Pass 1: u = exp(q.v^T/sqrt(D)) -> fp16 hi/lo; inv rowsums.
// CTA: 128 i-rows, 256 thr (8 warps: 4m x 2n), j chunks of 128. occ 1.
// 3-term fp16 split (err ~2^-22).
// =====================================================================
#define PITCH 272
#define TILE_B (128 * PITCH)
#define OFF_QLO   0
#define OFF_VBUF(x) (TILE_B + (x) * (2 * TILE_B))
#define OFF_RS    (TILE_B + 4 * TILE_B)
#define P1_SMEM   (OFF_RS + 128 * 2 * 4)

__device__ __forceinline__ void stage_tile(uint32_t dst,
                                           const __half* src, int t) {
#pragma unroll
    for (int it = 0; it < 8; ++it) {
        int id = it * 256 + t;
        int r = id >> 4, c = id & 15;
        cp_async16(dst + r * PITCH + c * 16, src + r * 128 + c * 8);
    }
}

__global__ void __launch_bounds__(256, 1)
pass1_kernel() {
    extern __shared__ char sm[];
    const uint32_t smb = smem_u32(sm);
    float* rsbuf = (float*)(sm + OFF_RS);

    const int b  = blockIdx.y;
    const int i0 = blockIdx.x * 128;
    const int t  = threadIdx.x;
    const int w  = t >> 5;
    const int l  = t & 31;
    const int wm = w & 3;
    const int wn = w >> 2;

    const __half* qhg = g_qhi + ((size_t)b * SEQ + i0) * DIM;
    const __half* qlg = g_qlo + ((size_t)b * SEQ + i0) * DIM;
    const __half* vhg = g_vhi + (size_t)b * SEQ * DIM;
    const __half* vlg = g_vlo + (size_t)b * SEQ * DIM;

    const int rA = (l & 7) + ((l >> 3) & 1) * 8;
    const int cA = (l >> 4) * 8;
    const int rB = (l & 7) + (l >> 4) * 8;
    const int cB = ((l >> 3) & 1) * 8;

    stage_tile(smb + OFF_VBUF(0), qhg, t);
    stage_tile(smb + OFF_QLO,     qlg, t);
    CP_COMMIT();
    CP_WAIT0();
    __syncthreads();

    unsigned qh[2][8][4];
#pragma unroll
    for (int f = 0; f < 2; ++f)
#pragma unroll
        for (int k8 = 0; k8 < 8; ++k8) {
            uint32_t addr = smb + OFF_VBUF(0) +
                (wm * 32 + f * 16 + rA) * PITCH + (k8 * 16 + cA) * 2;
            ldm4(qh[f][k8], addr);
        }
    __syncthreads();

    uint32_t qloA[2];
#pragma unroll
    for (int f = 0; f < 2; ++f)
        qloA[f] = smb + OFF_QLO + (wm * 32 + f * 16 + rA) * PITCH + cA * 2;

    uint32_t bRow[4];
#pragma unroll
    for (int p = 0; p < 4; ++p)
        bRow[p] = (wn * 64 + p * 16 + rB) * PITCH + cB * 2;

    stage_tile(smb + OFF_VBUF(0),          vhg, t);
    stage_tile(smb + OFF_VBUF(0) + TILE_B, vlg, t);
    CP_COMMIT();
    stage_tile(smb + OFF_VBUF(1),          vhg + 128 * DIM, t);
    stage_tile(smb + OFF_VBUF(1) + TILE_B, vlg + 128 * DIM, t);
    CP_COMMIT();

    __half *uh[2], *ul[2];
#pragma unroll
    for (int f = 0; f < 2; ++f) {
        size_t base = ((size_t)(b * SEQ + i0 + wm * 32 + f * 16 + (l >> 2))) * SEQ
                      + wn * 64 + (l & 3) * 2;
        uh[f] = g_uhi + base;
        ul[f] = g_ulo + base;
    }

    float rs[2][2] = {{0.f, 0.f}, {0.f, 0.f}};
    const int NCHUNK = SEQ / 128;

    for (int c = 0; c < NCHUNK; ++c) {
        CP_WAIT1();
        __syncthreads();

        const uint32_t vh = smb + OFF_VBUF(c & 1);
        const uint32_t vl = vh + TILE_B;

        float acc[2][8][4];
#pragma unroll
        for (int f = 0; f < 2; ++f)
#pragma unroll
            for (int n = 0; n < 8; ++n)
#pragma unroll
                for (int x = 0; x < 4; ++x) acc[f][n][x] = 0.0f;

#pragma unroll
        for (int k8 = 0; k8 < 8; ++k8) {
            unsigned bh[4][4];
#pragma unroll
            for (int p = 0; p < 4; ++p)
                ldm4(bh[p], vh + bRow[p] + k8 * 32);
            unsigned al[2][4];
            ldm4(al[0], qloA[0] + k8 * 32);
            ldm4(al[1], qloA[1] + k8 * 32);
#pragma unroll
            for (int p = 0; p < 4; ++p)
#pragma unroll
                for (int h = 0; h < 2; ++h) {
                    const unsigned* bb = &bh[p][2 * h];
                    int n = 2 * p + h;
                    mma16816(acc[0][n], qh[0][k8], bb);
                    mma16816(acc[1][n], qh[1][k8], bb);
                    mma16816(acc[0][n], al[0], bb);
                    mma16816(acc[1][n], al[1], bb);
                }
            unsigned bl[4][4];
#pragma unroll
            for (int p = 0; p < 4; ++p)
                ldm4(bl[p], vl + bRow[p] + k8 * 32);
#pragma unroll
            for (int p = 0; p < 4; ++p)
#pragma unroll
                for (int h = 0; h < 2; ++h) {
                    const unsigned* bb = &bl[p][2 * h];
                    int n = 2 * p + h;
                    mma16816(acc[0][n], qh[0][k8], bb);
                    mma16816(acc[1][n], qh[1][k8], bb);
                }
        }

        __syncthreads();

        if (c + 2 < NCHUNK) {
            const uint32_t nb = smb + OFF_VBUF(c & 1);
            stage_tile(nb,          vhg + (size_t)(c + 2) * 128 * DIM, t);
            stage_tile(nb + TILE_B, vlg + (size_t)(c + 2) * 128 * DIM, t);
        }
        CP_COMMIT();

        // ---- epilogue: exp + rowsum + fp16 hi/lo store ----
#pragma unroll
        for (int f = 0; f < 2; ++f) {
#pragma unroll
            for (int n = 0; n < 8; ++n) {
                float e0 = exp2f(acc[f][n][0] * EXP2_SCALE);
                float e1 = exp2f(acc[f][n][1] * EXP2_SCALE);
                float e2 = exp2f(acc[f][n][2] * EXP2_SCALE);
                float e3 = exp2f(acc[f][n][3] * EXP2_SCALE);
                rs[f][0] += e0 + e1;
                rs[f][1] += e2 + e3;
                __half2 h01 = __floats2half2_rn(e0, e1);
                __half2 h23 = __floats2half2_rn(e2, e3);
                __half2 l01 = __floats2half2_rn(e0 - __low2float(h01),
                                                e1 - __high2float(h01));
                __half2 l23 = __floats2half2_rn(e2 - __low2float(h23),
                                                e3 - __high2float(h23));
                int o0 = c * 128 + n * 8;
                *(__half2*)(uh[f] + o0)           = h01;
                *(__half2*)(uh[f] + o0 + 8 * SEQ) = h23;
                *(__half2*)(ul[f] + o0)           = l01;
                *(__half2*)(ul[f] + o0 + 8 * SEQ) = l23;
            }
        }
    }

#pragma unroll
    for (int f = 0; f < 2; ++f)
#pragma unroll
        for (int h = 0; h < 2; ++h) {
            rs[f][h] += __shfl_xor_sync(0xffffffffu, rs[f][h], 1);
            rs[f][h] += __shfl_xor_sync(0xffffffffu, rs[f][h], 2);
        }
    if ((l & 3) == 0) {
#pragma unroll
        for (int f = 0; f < 2; ++f)
#pragma unroll
            for (int h = 0; h < 2; ++h) {
                int row = wm * 32 + f * 16 + h * 8 + (l >> 2);
                rsbuf[row * 2 + wn] = rs[f][h];
            }
    }
    __syncthreads();
    if (t < 128)
        g_inv_rs[b * SEQ + i0 + t] = 1.0f / (rsbuf[t * 2] + rsbuf[t * 2 + 1]);
}

// =====================================================================
// Pass 2 (2-term fp16): out[j,d] = sum_i u[i,j]*w_hi[i,d],
// terms u_hi.w_hi + u_lo.w_hi; attn = (u_hi+u_lo)*inv_rs.
// CTA: 64 j x 128 d, 256 thr (8 warps: 2m x 4n, warp tile 32x32).
// 64 chunks of 32 i, 4-stage cp.async pipeline. occ 2.
// =====================================================================
#define P2_I    32
#define UPITCH  144
#define WPITCH  272
#define USZ     (P2_I * UPITCH)            // 4608
#define WSZ     (P2_I * WPITCH)            // 8704
#define STG_SZ  (2 * USZ + WSZ)            // 17920
#define OFF_UH(s) ((s) * STG_SZ)
#define OFF_UL(s) ((s) * STG_SZ + USZ)
#define OFF_WH(s) ((s) * STG_SZ + 2 * USZ)
#define P2_SMEM   (4 * STG_SZ)             // 71680

__device__ __forceinline__ void stage_u32r(uint32_t dst,
                                           const __half* src, int t) {
    int r = t >> 3, c = t & 7;
    cp_async16(dst + r * UPITCH + c * 16, src + (size_t)r * SEQ + c * 8);
}
__device__ __forceinline__ void stage_w32r(uint32_t dst,
                                           const __half* src, int t) {
#pragma unroll
    for (int it = 0; it < 2; ++it) {
        int id = it * 256 + t;
        int r = id >> 4, c = id & 15;
        cp_async16(dst + r * WPITCH + c * 16, src + r * DIM + c * 8);
    }
}

__global__ void __launch_bounds__(256, 2)
pass2_kernel(float* __restrict__ attn, float* __restrict__ out) {
    extern __shared__ char sm[];
    const uint32_t smb = smem_u32(sm);

    const int b  = blockIdx.y;
    const int j0 = blockIdx.x * 64;
    const int t  = threadIdx.x;
    const int w  = t >> 5;
    const int l  = t & 31;
    const int wm = w & 1;        // j-subtile (32)
    const int wn = w >> 1;       // d-subtile (32)

    float* ab = attn + (size_t)b * SEQ * SEQ;
    const __half* uhg = g_uhi + (size_t)b * SEQ * SEQ + j0;
    const __half* ulg = g_ulo + (size_t)b * SEQ * SEQ + j0;
    const __half* whg = g_vhi + (size_t)b * SEQ * DIM;
    const float* irs = g_inv_rs + b * SEQ;
    float*       ob  = out + (size_t)b * SEQ * DIM;

    const int rAT = (l & 7) + ((l >> 4) & 1) * 8;
    const int cAT = ((l >> 3) & 1) * 8;
    const int rBT = (l & 7) + ((l >> 3) & 1) * 8;
    const int cBT = (l >> 4) * 8;

    const int NCHUNK = SEQ / P2_I;   // 64

    // prologue: stages 0,1,2
#pragma unroll
    for (int c = 0; c < 3; ++c) {
        stage_u32r(smb + OFF_UH(c), uhg + (size_t)c * P2_I * SEQ, t);
        stage_u32r(smb + OFF_UL(c), ulg + (size_t)c * P2_I * SEQ, t);
        stage_w32r(smb + OFF_WH(c), whg + (size_t)c * P2_I * DIM, t);
        CP_COMMIT();
    }

    float acc[2][4][4];
#pragma unroll
    for (int f = 0; f < 2; ++f)
#pragma unroll
        for (int n = 0; n < 4; ++n)
#pragma unroll
            for (int x = 0; x < 4; ++x) acc[f][n][x] = 0.0f;

    for (int c = 0; c < NCHUNK; ++c) {
        const int st  = c & 3;
        const int i0c = c * P2_I;

        CP_WAIT2();
        __syncthreads();

        if (c + 3 < NCHUNK) {
            const int ns = (c + 3) & 3;
            const size_t io = (size_t)(c + 3) * P2_I;
            stage_u32r(smb + OFF_UH(ns), uhg + io * SEQ, t);
            stage_u32r(smb + OFF_UL(ns), ulg + io * SEQ, t);
            stage_w32r(smb + OFF_WH(ns), whg + io * DIM, t);
        }
        CP_COMMIT();

        // ---- attn write: (u_hi + u_lo)*inv_rs -> gmem ----
        {
            int row = t >> 3, g = t & 7;
            float s = __ldg(irs + i0c + row);
            uint32_t ha = smb + OFF_UH(st) + row * UPITCH + g * 16;
            uint32_t la = smb + OFF_UL(st) + row * UPITCH + g * 16;
            unsigned hr[4], lr[4];
            asm volatile("ld.shared.v4.b32 {%0,%1,%2,%3}, [%4];"
                         : "=r"(hr[0]), "=r"(hr[1]), "=r"(hr[2]), "=r"(hr[3]) : "r"(ha));
            asm volatile("ld.shared.v4.b32 {%0,%1,%2,%3}, [%4];"
                         : "=r"(lr[0]), "=r"(lr[1]), "=r"(lr[2]), "=r"(lr[3]) : "r"(la));
            float o[8];
#pragma unroll
            for (int x = 0; x < 4; ++x) {
                __half2 h2 = *(__half2*)&hr[x];
                __half2 l2 = *(__half2*)&lr[x];
                o[2 * x + 0] = (__low2float(h2)  + __low2float(l2))  * s;
                o[2 * x + 1] = (__high2float(h2) + __high2float(l2)) * s;
            }
            float* grow = ab + (size_t)(i0c + row) * SEQ + j0 + g * 8;
            *(float4*)(grow)     = make_float4(o[0], o[1], o[2], o[3]);
            *(float4*)(grow + 4) = make_float4(o[4], o[5], o[6], o[7]);
        }

        // ---- MMA: 2 terms ----
        const uint32_t UH = smb + OFF_UH(st);
        const uint32_t UL = smb + OFF_UL(st);
        const uint32_t WH = smb + OFF_WH(st);
#pragma unroll
        for (int k8 = 0; k8 < P2_I / 16; ++k8) {
            unsigned ahf[2][4], alf[2][4];
#pragma unroll
            for (int f = 0; f < 2; ++f) {
                uint32_t coff = (k8 * 16 + rAT) * UPITCH +
                                (wm * 32 + f * 16 + cAT) * 2;
                ldm4t(ahf[f], UH + coff);
                ldm4t(alf[f], UL + coff);
            }
            unsigned bh[2][4];
#pragma unroll
            for (int p = 0; p < 2; ++p) {
                uint32_t coff = (k8 * 16 + rBT) * WPITCH +
                                (wn * 32 + p * 16 + cBT) * 2;
                ldm4t(bh[p], WH + coff);
            }
#pragma unroll
            for (int p = 0; p < 2; ++p)
#pragma unroll
                for (int h = 0; h < 2; ++h) {
                    int n = 2 * p + h;
#pragma unroll
                    for (int f = 0; f < 2; ++f) {
                        mma16816(acc[f][n], ahf[f], &bh[p][2 * h]);  // hi.hi
                        mma16816(acc[f][n], alf[f], &bh[p][2 * h]);  // lo.hi
                    }
                }
        }
    }

    // ---- store out[j,d] ----
#pragma unroll
    for (int f = 0; f < 2; ++f) {
        int jr = j0 + wm * 32 + f * 16 + (l >> 2);
        float* r0 = ob + (size_t)jr * DIM + wn * 32 + (l & 3) * 2;
#pragma unroll
        for (int n = 0; n < 4; ++n) {
            *(float2*)(r0 + n * 8)           = make_float2(acc[f][n][0], acc[f][n][1]);
            *(float2*)(r0 + n * 8 + 8 * DIM) = make_float2(acc[f][n][2], acc[f][n][3]);
        }
    }
}

// =====================================================================
extern "C" void kernel_launch(void* const* d_in, const int* in_sizes, int n_in,
                              void* d_out, int out_size) {
    const float* q = (const float*)d_in[0];
    // d_in[1] (k) unused by the reference
    const float* v = (const float*)d_in[2];

    float* out  = (float*)d_out;                      // [8,2048,128]
    float* attn = out + (size_t)BATCH * SEQ * DIM;    // [8,2048,2048]

    cudaFuncSetAttribute(pass1_kernel,
                         cudaFuncAttributeMaxDynamicSharedMemorySize, P1_SMEM);
    cudaFuncSetAttribute(pass2_kernel,
                         cudaFuncAttributeMaxDynamicSharedMemorySize, P2_SMEM);

    split_kernel<<<(BATCH * SEQ * DIM) / (256 * 4), 256>>>(q, v);

    dim3 g1(SEQ / 128, BATCH);
    pass1_kernel<<<g1, 256, P1_SMEM>>>();

    wsplit_kernel<<<(BATCH * SEQ * DIM) / (256 * 4), 256>>>(v);

    dim3 g2(SEQ / 64, BATCH);
    pass2_kernel<<<g2, 256, P2_SMEM>>>(attn, out);
}

// round 16
// speedup vs baseline: 1.4614x; 1.1013x over previous
#include <cuda_runtime.h>
#include <cuda_fp16.h>
#include <cstdint>

#define BATCH 8
#define SEQ   2048
#define DIM   128
#define EXP2_SCALE (0.08838834764831843f * 1.44269504088896340f)

typedef unsigned long long ull;

// ---------------- device scratch ----------------
__device__ float g_inv_rs[BATCH * SEQ];
__device__ __align__(16) __half g_qhi[BATCH * SEQ * DIM];
__device__ __align__(16) __half g_qlo[BATCH * SEQ * DIM];
__device__ __align__(16) __half g_vhi[BATCH * SEQ * DIM];  // w_hi after pass1
__device__ __align__(16) __half g_uhi[(size_t)BATCH * SEQ * SEQ];
__device__ __align__(16) __half g_ulo[(size_t)BATCH * SEQ * SEQ];

// ---------------- cp.async ----------------
__device__ __forceinline__ void cp_async16(uint32_t smem_dst, const void* gsrc) {
    asm volatile("cp.async.ca.shared.global [%0], [%1], 16;\n"
                 :: "r"(smem_dst), "l"(gsrc));
}
#define CP_COMMIT() asm volatile("cp.async.commit_group;\n" ::: "memory")
#define CP_WAIT0()  asm volatile("cp.async.wait_group 0;\n" ::: "memory")
#define CP_WAIT1()  asm volatile("cp.async.wait_group 1;\n" ::: "memory")
#define CP_WAIT2()  asm volatile("cp.async.wait_group 2;\n" ::: "memory")

__device__ __forceinline__ uint32_t smem_u32(const void* p) {
    uint32_t a;
    asm("{ .reg .u64 t; cvta.to.shared.u64 t, %1; cvt.u32.u64 %0, t; }"
        : "=r"(a) : "l"(p));
    return a;
}

// ---------------- mma / ldmatrix (fp16) ----------------
__device__ __forceinline__ void ldm4(unsigned* r, uint32_t addr) {
    asm volatile("ldmatrix.sync.aligned.m8n8.x4.shared.b16 {%0,%1,%2,%3}, [%4];"
                 : "=r"(r[0]), "=r"(r[1]), "=r"(r[2]), "=r"(r[3]) : "r"(addr));
}
__device__ __forceinline__ void ldm4t(unsigned* r, uint32_t addr) {
    asm volatile("ldmatrix.sync.aligned.m8n8.x4.trans.shared.b16 {%0,%1,%2,%3}, [%4];"
                 : "=r"(r[0]), "=r"(r[1]), "=r"(r[2]), "=r"(r[3]) : "r"(addr));
}
__device__ __forceinline__ void mma16816(float* d, const unsigned* a,
                                         const unsigned* b) {
    asm volatile(
        "mma.sync.aligned.m16n8k16.row.col.f32.f16.f16.f32 "
        "{%0,%1,%2,%3}, {%4,%5,%6,%7}, {%8,%9}, {%0,%1,%2,%3};"
        : "+f"(d[0]), "+f"(d[1]), "+f"(d[2]), "+f"(d[3])
        : "r"(a[0]), "r"(a[1]), "r"(a[2]), "r"(a[3]), "r"(b[0]), "r"(b[1]));
}

// =====================================================================
// split kernel: q -> fp16 hi/lo, v -> fp16 hi  (vlo unused in 2-term p1)
// =====================================================================
__global__ void __launch_bounds__(256)
split_kernel(const float* __restrict__ q, const float* __restrict__ v) {
    int i = (blockIdx.x * 256 + threadIdx.x) * 4;
    float4 fq = *(const float4*)(q + i);
    float4 fv = *(const float4*)(v + i);
    float xq[4] = {fq.x, fq.y, fq.z, fq.w};
    float xv[4] = {fv.x, fv.y, fv.z, fv.w};
    __half qh[4], ql[4], vh[4];
#pragma unroll
    for (int j = 0; j < 4; ++j) {
        qh[j] = __float2half_rn(xq[j]);
        ql[j] = __float2half_rn(xq[j] - __half2float(qh[j]));
        vh[j] = __float2half_rn(xv[j]);
    }
    *(ull*)(g_qhi + i) = *(ull*)qh;
    *(ull*)(g_qlo + i) = *(ull*)ql;
    *(ull*)(g_vhi + i) = *(ull*)vh;
}

// =====================================================================
// wsplit kernel (after pass1): w_hi[i,d] = fp16(inv_rs[i]*v[i,d])
// =====================================================================
__global__ void __launch_bounds__(256)
wsplit_kernel(const float* __restrict__ v) {
    int e = (blockIdx.x * 256 + threadIdx.x) * 4;
    float s = g_inv_rs[e >> 7];
    float4 f = *(const float4*)(v + e);
    __half wh[4];
    wh[0] = __float2half_rn(f.x * s);
    wh[1] = __float2half_rn(f.y * s);
    wh[2] = __float2half_rn(f.z * s);
    wh[3] = __float2half_rn(f.w * s);
    *(ull*)(g_vhi + e) = *(ull*)wh;
}

// =====================================================================
// Pass 1 (2-term fp16): u = exp(q.v^T/sqrt(D)) -> fp16 hi/lo; inv rowsums.
// terms: qhi.vhi + qlo.vhi  (qhi.vlo dropped, err ~2.7e-4 on u)
// CTA: 64 i-rows, 256 thr (8 warps: 2m x 4n, warp tile 32x32),
// j chunks of 128. All operands ldmatrix'd from smem. occ 2.
// =====================================================================
#define PITCH 272
#define QTILE (64 * PITCH)                  // 17408
#define VTILE (128 * PITCH)                 // 34816
#define OFF_QHI   0
#define OFF_QLO   QTILE
#define OFF_VBUF(x) (2 * QTILE + (x) * VTILE)
#define OFF_RS    (2 * QTILE + 2 * VTILE)   // 104448
#define P1_SMEM   (OFF_RS + 64 * 4 * 4)     // 105472

__device__ __forceinline__ void stage_q64(uint32_t dst,
                                          const __half* src, int t) {
#pragma unroll
    for (int it = 0; it < 4; ++it) {
        int id = it * 256 + t;
        int r = id >> 4, c = id & 15;
        cp_async16(dst + r * PITCH + c * 16, src + r * 128 + c * 8);
    }
}
__device__ __forceinline__ void stage_v128(uint32_t dst,
                                           const __half* src, int t) {
#pragma unroll
    for (int it = 0; it < 8; ++it) {
        int id = it * 256 + t;
        int r = id >> 4, c = id & 15;
        cp_async16(dst + r * PITCH + c * 16, src + r * 128 + c * 8);
    }
}

__global__ void __launch_bounds__(256, 2)
pass1_kernel() {
    extern __shared__ char sm[];
    const uint32_t smb = smem_u32(sm);
    float* rsbuf = (float*)(sm + OFF_RS);   // [64][4]

    const int b  = blockIdx.y;
    const int i0 = blockIdx.x * 64;
    const int t  = threadIdx.x;
    const int w  = t >> 5;
    const int l  = t & 31;
    const int wm = w & 1;        // i-subtile (32 rows)
    const int wn = w >> 1;       // j-subtile (32 cols)

    const __half* qhg = g_qhi + ((size_t)b * SEQ + i0) * DIM;
    const __half* qlg = g_qlo + ((size_t)b * SEQ + i0) * DIM;
    const __half* vhg = g_vhi + (size_t)b * SEQ * DIM;

    const int rA = (l & 7) + ((l >> 3) & 1) * 8;
    const int cA = (l >> 4) * 8;
    const int rB = (l & 7) + (l >> 4) * 8;
    const int cB = ((l >> 3) & 1) * 8;

    // A row offsets (same for qhi/qlo regions)
    uint32_t aRow[2];
#pragma unroll
    for (int f = 0; f < 2; ++f)
        aRow[f] = (wm * 32 + f * 16 + rA) * PITCH + cA * 2;
    // B row offsets (two 16-col frag pairs inside warp's 32-col block)
    uint32_t bRow[2];
#pragma unroll
    for (int p = 0; p < 2; ++p)
        bRow[p] = (wn * 32 + p * 16 + rB) * PITCH + cB * 2;

    // prologue: q tiles + v chunk 0 (group 1), v chunk 1 (group 2)
    stage_q64(smb + OFF_QHI, qhg, t);
    stage_q64(smb + OFF_QLO, qlg, t);
    stage_v128(smb + OFF_VBUF(0), vhg, t);
    CP_COMMIT();
    stage_v128(smb + OFF_VBUF(1), vhg + 128 * DIM, t);
    CP_COMMIT();

    // per-thread u output pointers
    __half *uh[2], *ul[2];
#pragma unroll
    for (int f = 0; f < 2; ++f) {
        size_t base = ((size_t)(b * SEQ + i0 + wm * 32 + f * 16 + (l >> 2))) * SEQ
                      + wn * 32 + (l & 3) * 2;
        uh[f] = g_uhi + base;
        ul[f] = g_ulo + base;
    }

    float rs[2][2] = {{0.f, 0.f}, {0.f, 0.f}};
    const int NCHUNK = SEQ / 128;   // 16

    for (int c = 0; c < NCHUNK; ++c) {
        CP_WAIT1();
        __syncthreads();   // chunk c landed (q tiles too at c=0)

        const uint32_t vh = smb + OFF_VBUF(c & 1);

        float acc[2][4][4];
#pragma unroll
        for (int f = 0; f < 2; ++f)
#pragma unroll
            for (int n = 0; n < 4; ++n)
#pragma unroll
                for (int x = 0; x < 4; ++x) acc[f][n][x] = 0.0f;

#pragma unroll
        for (int k8 = 0; k8 < 8; ++k8) {
            unsigned ah[2][4], al[2][4], bh[2][4];
#pragma unroll
            for (int f = 0; f < 2; ++f) {
                ldm4(ah[f], smb + OFF_QHI + aRow[f] + k8 * 32);
                ldm4(al[f], smb + OFF_QLO + aRow[f] + k8 * 32);
            }
#pragma unroll
            for (int p = 0; p < 2; ++p)
                ldm4(bh[p], vh + bRow[p] + k8 * 32);
#pragma unroll
            for (int p = 0; p < 2; ++p)
#pragma unroll
                for (int h = 0; h < 2; ++h) {
                    int n = 2 * p + h;
#pragma unroll
                    for (int f = 0; f < 2; ++f) {
                        mma16816(acc[f][n], ah[f], &bh[p][2 * h]);  // hi.hi
                        mma16816(acc[f][n], al[f], &bh[p][2 * h]);  // lo.hi
                    }
                }
        }

        __syncthreads();   // all warps done reading buf (c&1)

        if (c + 2 < NCHUNK)
            stage_v128(smb + OFF_VBUF(c & 1),
                       vhg + (size_t)(c + 2) * 128 * DIM, t);
        CP_COMMIT();

        // ---- epilogue: exp + rowsum + fp16 hi/lo store ----
#pragma unroll
        for (int f = 0; f < 2; ++f) {
#pragma unroll
            for (int n = 0; n < 4; ++n) {
                float e0 = exp2f(acc[f][n][0] * EXP2_SCALE);
                float e1 = exp2f(acc[f][n][1] * EXP2_SCALE);
                float e2 = exp2f(acc[f][n][2] * EXP2_SCALE);
                float e3 = exp2f(acc[f][n][3] * EXP2_SCALE);
                rs[f][0] += e0 + e1;
                rs[f][1] += e2 + e3;
                __half2 h01 = __floats2half2_rn(e0, e1);
                __half2 h23 = __floats2half2_rn(e2, e3);
                __half2 l01 = __floats2half2_rn(e0 - __low2float(h01),
                                                e1 - __high2float(h01));
                __half2 l23 = __floats2half2_rn(e2 - __low2float(h23),
                                                e3 - __high2float(h23));
                int o0 = c * 128 + n * 8;
                *(__half2*)(uh[f] + o0)           = h01;
                *(__half2*)(uh[f] + o0 + 8 * SEQ) = h23;
                *(__half2*)(ul[f] + o0)           = l01;
                *(__half2*)(ul[f] + o0 + 8 * SEQ) = l23;
            }
        }
    }

    // ---- rowsums: quad-reduce, combine across 4 wn warps via smem ----
#pragma unroll
    for (int f = 0; f < 2; ++f)
#pragma unroll
        for (int h = 0; h < 2; ++h) {
            rs[f][h] += __shfl_xor_sync(0xffffffffu, rs[f][h], 1);
            rs[f][h] += __shfl_xor_sync(0xffffffffu, rs[f][h], 2);
        }
    if ((l & 3) == 0) {
#pragma unroll
        for (int f = 0; f < 2; ++f)
#pragma unroll
            for (int h = 0; h < 2; ++h) {
                int row = wm * 32 + f * 16 + h * 8 + (l >> 2);
                rsbuf[row * 4 + wn] = rs[f][h];
            }
    }
    __syncthreads();
    if (t < 64)
        g_inv_rs[b * SEQ + i0 + t] = 1.0f /
            (rsbuf[t * 4] + rsbuf[t * 4 + 1] + rsbuf[t * 4 + 2] + rsbuf[t * 4 + 3]);
}

// =====================================================================
// Pass 2 (2-term fp16, unchanged): out[j,d] = sum_i u[i,j]*w_hi[i,d],
// terms u_hi.w_hi + u_lo.w_hi; attn = (u_hi+u_lo)*inv_rs.
// CTA: 64 j x 128 d, 256 thr, 64 chunks of 32 i, 4-stage pipeline. occ 2.
// =====================================================================
#define P2_I    32
#define UPITCH  144
#define WPITCH  272
#define USZ     (P2_I * UPITCH)
#define WSZ     (P2_I * WPITCH)
#define STG_SZ  (2 * USZ + WSZ)
#define OFF_UH(s) ((s) * STG_SZ)
#define OFF_UL(s) ((s) * STG_SZ + USZ)
#define OFF_WH(s) ((s) * STG_SZ + 2 * USZ)
#define P2_SMEM   (4 * STG_SZ)

__device__ __forceinline__ void stage_u32r(uint32_t dst,
                                           const __half* src, int t) {
    int r = t >> 3, c = t & 7;
    cp_async16(dst + r * UPITCH + c * 16, src + (size_t)r * SEQ + c * 8);
}
__device__ __forceinline__ void stage_w32r(uint32_t dst,
                                           const __half* src, int t) {
#pragma unroll
    for (int it = 0; it < 2; ++it) {
        int id = it * 256 + t;
        int r = id >> 4, c = id & 15;
        cp_async16(dst + r * WPITCH + c * 16, src + r * DIM + c * 8);
    }
}

__global__ void __launch_bounds__(256, 2)
pass2_kernel(float* __restrict__ attn, float* __restrict__ out) {
    extern __shared__ char sm[];
    const uint32_t smb = smem_u32(sm);

    const int b  = blockIdx.y;
    const int j0 = blockIdx.x * 64;
    const int t  = threadIdx.x;
    const int w  = t >> 5;
    const int l  = t & 31;
    const int wm = w & 1;
    const int wn = w >> 1;

    float* ab = attn + (size_t)b * SEQ * SEQ;
    const __half* uhg = g_uhi + (size_t)b * SEQ * SEQ + j0;
    const __half* ulg = g_ulo + (size_t)b * SEQ * SEQ + j0;
    const __half* whg = g_vhi + (size_t)b * SEQ * DIM;
    const float* irs = g_inv_rs + b * SEQ;
    float*       ob  = out + (size_t)b * SEQ * DIM;

    const int rAT = (l & 7) + ((l >> 4) & 1) * 8;
    const int cAT = ((l >> 3) & 1) * 8;
    const int rBT = (l & 7) + ((l >> 3) & 1) * 8;
    const int cBT = (l >> 4) * 8;

    const int NCHUNK = SEQ / P2_I;   // 64

#pragma unroll
    for (int c = 0; c < 3; ++c) {
        stage_u32r(smb + OFF_UH(c), uhg + (size_t)c * P2_I * SEQ, t);
        stage_u32r(smb + OFF_UL(c), ulg + (size_t)c * P2_I * SEQ, t);
        stage_w32r(smb + OFF_WH(c), whg + (size_t)c * P2_I * DIM, t);
        CP_COMMIT();
    }

    float acc[2][4][4];
#pragma unroll
    for (int f = 0; f < 2; ++f)
#pragma unroll
        for (int n = 0; n < 4; ++n)
#pragma unroll
            for (int x = 0; x < 4; ++x) acc[f][n][x] = 0.0f;

    for (int c = 0; c < NCHUNK; ++c) {
        const int st  = c & 3;
        const int i0c = c * P2_I;

        CP_WAIT2();
        __syncthreads();

        if (c + 3 < NCHUNK) {
            const int ns = (c + 3) & 3;
            const size_t io = (size_t)(c + 3) * P2_I;
            stage_u32r(smb + OFF_UH(ns), uhg + io * SEQ, t);
            stage_u32r(smb + OFF_UL(ns), ulg + io * SEQ, t);
            stage_w32r(smb + OFF_WH(ns), whg + io * DIM, t);
        }
        CP_COMMIT();

        // ---- attn write: (u_hi + u_lo)*inv_rs -> gmem ----
        {
            int row = t >> 3, g = t & 7;
            float s = __ldg(irs + i0c + row);
            uint32_t ha = smb + OFF_UH(st) + row * UPITCH + g * 16;
            uint32_t la = smb + OFF_UL(st) + row * UPITCH + g * 16;
            unsigned hr[4], lr[4];
            asm volatile("ld.shared.v4.b32 {%0,%1,%2,%3}, [%4];"
                         : "=r"(hr[0]), "=r"(hr[1]), "=r"(hr[2]), "=r"(hr[3]) : "r"(ha));
            asm volatile("ld.shared.v4.b32 {%0,%1,%2,%3}, [%4];"
                         : "=r"(lr[0]), "=r"(lr[1]), "=r"(lr[2]), "=r"(lr[3]) : "r"(la));
            float o[8];
#pragma unroll
            for (int x = 0; x < 4; ++x) {
                __half2 h2 = *(__half2*)&hr[x];
                __half2 l2 = *(__half2*)&lr[x];
                o[2 * x + 0] = (__low2float(h2)  + __low2float(l2))  * s;
                o[2 * x + 1] = (__high2float(h2) + __high2float(l2)) * s;
            }
            float* grow = ab + (size_t)(i0c + row) * SEQ + j0 + g * 8;
            *(float4*)(grow)     = make_float4(o[0], o[1], o[2], o[3]);
            *(float4*)(grow + 4) = make_float4(o[4], o[5], o[6], o[7]);
        }

        // ---- MMA: 2 terms ----
        const uint32_t UH = smb + OFF_UH(st);
        const uint32_t UL = smb + OFF_UL(st);
        const uint32_t WH = smb + OFF_WH(st);
#pragma unroll
        for (int k8 = 0; k8 < P2_I / 16; ++k8) {
            unsigned ahf[2][4], alf[2][4];
#pragma unroll
            for (int f = 0; f < 2; ++f) {
                uint32_t coff = (k8 * 16 + rAT) * UPITCH +
                                (wm * 32 + f * 16 + cAT) * 2;
                ldm4t(ahf[f], UH + coff);
                ldm4t(alf[f], UL + coff);
            }
            unsigned bh[2][4];
#pragma unroll
            for (int p = 0; p < 2; ++p) {
                uint32_t coff = (k8 * 16 + rBT) * WPITCH +
                                (wn * 32 + p * 16 + cBT) * 2;
                ldm4t(bh[p], WH + coff);
            }
#pragma unroll
            for (int p = 0; p < 2; ++p)
#pragma unroll
                for (int h = 0; h < 2; ++h) {
                    int n = 2 * p + h;
#pragma unroll
                    for (int f = 0; f < 2; ++f) {
                        mma16816(acc[f][n], ahf[f], &bh[p][2 * h]);
                        mma16816(acc[f][n], alf[f], &bh[p][2 * h]);
                    }
                }
        }
    }

    // ---- store out[j,d] ----
#pragma unroll
    for (int f = 0; f < 2; ++f) {
        int jr = j0 + wm * 32 + f * 16 + (l >> 2);
        float* r0 = ob + (size_t)jr * DIM + wn * 32 + (l & 3) * 2;
#pragma unroll
        for (int n = 0; n < 4; ++n) {
            *(float2*)(r0 + n * 8)           = make_float2(acc[f][n][0], acc[f][n][1]);
            *(float2*)(r0 + n * 8 + 8 * DIM) = make_float2(acc[f][n][2], acc[f][n][3]);
        }
    }
}

// =====================================================================
extern "C" void kernel_launch(void* const* d_in, const int* in_sizes, int n_in,
                              void* d_out, int out_size) {
    const float* q = (const float*)d_in[0];
    // d_in[1] (k) unused by the reference
    const float* v = (const float*)d_in[2];

    float* out  = (float*)d_out;                      // [8,2048,128]
    float* attn = out + (size_t)BATCH * SEQ * DIM;    // [8,2048,2048]

    cudaFuncSetAttribute(pass1_kernel,
                         cudaFuncAttributeMaxDynamicSharedMemorySize, P1_SMEM);
    cudaFuncSetAttribute(pass2_kernel,
                         cudaFuncAttributeMaxDynamicSharedMemorySize, P2_SMEM);

    split_kernel<<<(BATCH * SEQ * DIM) / (256 * 4), 256>>>(q, v);

    dim3 g1(SEQ / 64, BATCH);
    pass1_kernel<<<g1, 256, P1_SMEM>>>();

    wsplit_kernel<<<(BATCH * SEQ * DIM) / (256 * 4), 256>>>(v);

    dim3 g2(SEQ / 64, BATCH);
    pass2_kernel<<<g2, 256, P2_SMEM>>>(attn, out);
}